// round 15
// baseline (speedup 1.0000x reference)
#include <cuda_runtime.h>
#include <cuda_fp16.h>
#include <math.h>
#include <stdint.h>

// ---------------- problem constants ----------------
#define NN      50000
#define EE      800000
#define TOTE    (EE + NN)      // 850000 edges incl self loops
#define FIN     256
#define HH      4
#define CC      128
#define HC      (HH * CC)      // 512
#define VV      3
#define GN      (VV * HC)      // 1536
#define NK      8              // K chunks of 32

// ---------------- device scratch ----------------
__device__ __half g_h[(size_t)VV * NN * HC];      // 153.6 MB
__device__ __half g_xf16[(size_t)NN * FIN];       // 25.6 MB
__device__ __half g_wf16[(size_t)VV * HC * FIN];  // 0.79 MB (Wt[v][n][k])
__device__ float g_views[(size_t)VV * NN * CC];   // 76.8 MB
__device__ float g_ssrc[(size_t)VV * NN * HH];
__device__ float g_sdst[(size_t)VV * NN * HH];
__device__ int   g_count[VV * NN];
__device__ int   g_cursor[VV * NN];
__device__ int   g_indptr[VV * (NN + 1)];
__device__ int   g_btot[VV * 64];
__device__ int   g_boff[VV * 64];
__device__ int   g_csrc[VV * TOTE];
__device__ float g_cex[(size_t)VV * TOTE * HH];   // 40.8 MB

// ---------------- helpers ----------------
__device__ __forceinline__ uint32_t smem_u32(const void* p) {
    uint32_t a;
    asm("{ .reg .u64 t; cvta.to.shared.u64 t, %1; cvt.u32.u64 %0, t; }"
        : "=r"(a) : "l"(p));
    return a;
}

// 16B async copy, L1-bypass (.cg). pred=false -> zero-fill.
__device__ __forceinline__ void cp16(uint32_t dst, const void* src, bool pred) {
    int bytes = pred ? 16 : 0;
    asm volatile("cp.async.cg.shared.global [%0], [%1], 16, %2;"
                 :: "r"(dst), "l"(src), "r"(bytes));
}

__device__ __forceinline__ void mma_f16(float& c0, float& c1, float& c2, float& c3,
                                        uint32_t a0, uint32_t a1, uint32_t a2, uint32_t a3,
                                        uint32_t b0, uint32_t b1) {
    asm volatile(
        "mma.sync.aligned.m16n8k16.row.col.f32.f16.f16.f32 "
        "{%0,%1,%2,%3}, {%4,%5,%6,%7}, {%8,%9}, {%0,%1,%2,%3};"
        : "+f"(c0), "+f"(c1), "+f"(c2), "+f"(c3)
        : "r"(a0), "r"(a1), "r"(a2), "r"(a3), "r"(b0), "r"(b1));
}

// ---------------- 0) precision converts ----------------
__global__ void xcvt_kernel(const float* __restrict__ x) {
    int i = blockIdx.x * blockDim.x + threadIdx.x;
    if (i < NN * FIN / 4) {
        float4 v = *(const float4*)&x[(size_t)i * 4];
        uint2 o;
        ((__half2*)&o)[0] = __floats2half2_rn(v.x, v.y);
        ((__half2*)&o)[1] = __floats2half2_rn(v.z, v.w);
        *(uint2*)&g_xf16[(size_t)i * 4] = o;
    }
}

__global__ void wcvt_kernel(const float* __restrict__ W) {
    int i = blockIdx.x * blockDim.x + threadIdx.x;   // Wt[v][n][k]
    if (i < VV * HC * FIN) {
        int k = i & (FIN - 1);
        int n = (i >> 8) & (HC - 1);
        int v = i >> 17;
        g_wf16[i] = __float2half(W[((size_t)v * FIN + k) * HC + n]);
    }
}

// ---------------- 1) fp16 HMMA GEMM, 3-stage cp.async, 1 sync/iter -------
// BM=128 BN=128 BK=32; 256 thr = 8 warps (2m x 4n); warp tile 64x32.
#define AKP 40
#define BKP 40
#define ASTAGE (128 * AKP)     // halves per stage
#define BSTAGE (128 * BKP)
#define ABYTES (ASTAGE * 2)
#define BBYTES (BSTAGE * 2)
#define GEMM_DYN_SMEM (3 * (ABYTES + BBYTES))   // 61440 B
__global__ void gemm_f16_kernel(const float* __restrict__ a_src,
                                const float* __restrict__ a_dst) {
    extern __shared__ __half dyn_smem[];
    __half* As = dyn_smem;                    // 3 stages
    __half* Bt = dyn_smem + 3 * ASTAGE;       // 3 stages
    __shared__ float sps[128][4];
    __shared__ float spd[128][4];

    int tid = threadIdx.x;
    int warp = tid >> 5, lane = tid & 31;
    int wm = warp >> 2, wn = warp & 3;
    int grp = lane >> 2, qid = lane & 3;

    int mbase = blockIdx.y * 128;
    int nbase = blockIdx.x * 128;
    int v = nbase >> 9;
    int nc0 = nbase & 511;
    int head = nc0 >> 7;
    const __half* Ax = g_xf16;
    const __half* Bw = g_wf16 + (size_t)v * HC * FIN + (size_t)nc0 * FIN;

    uint32_t as_b = smem_u32(As);
    uint32_t bt_b = smem_u32(Bt);

    // fixed per-thread fill coords: 2 x 16B for A, 2 x 16B for B
    int r0l = tid >> 2;                 // 0..63
    int r1l = r0l + 64;                 // 64..127
    int ul  = (tid & 3) * 8;            // 0,8,16,24 (halves)
    int row0 = mbase + r0l, row1 = mbase + r1l;
    bool p0 = row0 < NN, p1 = row1 < NN;
    const __half* a0p = &Ax[(size_t)(p0 ? row0 : 0) * FIN + ul];
    const __half* a1p = &Ax[(size_t)(p1 ? row1 : 0) * FIN + ul];
    const __half* b0p = &Bw[(size_t)r0l * FIN + ul];
    const __half* b1p = &Bw[(size_t)r1l * FIN + ul];
    uint32_t asd0 = as_b + (uint32_t)((r0l * AKP + ul) * 2);
    uint32_t asd1 = as_b + (uint32_t)((r1l * AKP + ul) * 2);
    uint32_t btd0 = bt_b + (uint32_t)((r0l * BKP + ul) * 2);
    uint32_t btd1 = bt_b + (uint32_t)((r1l * BKP + ul) * 2);

    float acc[4][4][4];
#pragma unroll
    for (int mi = 0; mi < 4; mi++)
#pragma unroll
        for (int ni = 0; ni < 4; ni++)
#pragma unroll
            for (int r = 0; r < 4; r++) acc[mi][ni][r] = 0.0f;

    // prologue: chunks 0 and 1 into stages 0, 1
    cp16(asd0, a0p, p0);
    cp16(asd1, a1p, p1);
    cp16(btd0, b0p, true);
    cp16(btd1, b1p, true);
    asm volatile("cp.async.commit_group;" ::: "memory");
    cp16(asd0 + ABYTES, a0p + 32, p0);
    cp16(asd1 + ABYTES, a1p + 32, p1);
    cp16(btd0 + BBYTES, b0p + 32, true);
    cp16(btd1 + BBYTES, b1p + 32, true);
    asm volatile("cp.async.commit_group;" ::: "memory");

    for (int c = 0; c < NK; c++) {
        if (c == NK - 1)
            asm volatile("cp.async.wait_group 0;" ::: "memory");
        else
            asm volatile("cp.async.wait_group 1;" ::: "memory");
        __syncthreads();   // chunk c ready; stage (c-1)%3 free for reuse

        if (c + 2 < NK) {
            int k0 = (c + 2) * 32;
            uint32_t st = (uint32_t)((c + 2) % 3);
            uint32_t soA = st * ABYTES;
            uint32_t soB = st * BBYTES;
            cp16(asd0 + soA, a0p + k0, p0);
            cp16(asd1 + soA, a1p + k0, p1);
            cp16(btd0 + soB, b0p + k0, true);
            cp16(btd1 + soB, b1p + k0, true);
            asm volatile("cp.async.commit_group;" ::: "memory");
        }

        const __half* A_ = &As[(c % 3) * ASTAGE];
        const __half* B_ = &Bt[(c % 3) * BSTAGE];
#pragma unroll
        for (int kk = 0; kk < 2; kk++) {
            int ko = kk * 16;
            uint32_t af[4][4];
#pragma unroll
            for (int mi = 0; mi < 4; mi++) {
                int r0 = wm * 64 + mi * 16 + grp;
                af[mi][0] = *(const uint32_t*)&A_[r0 * AKP + ko + qid * 2];
                af[mi][1] = *(const uint32_t*)&A_[(r0 + 8) * AKP + ko + qid * 2];
                af[mi][2] = *(const uint32_t*)&A_[r0 * AKP + ko + qid * 2 + 8];
                af[mi][3] = *(const uint32_t*)&A_[(r0 + 8) * AKP + ko + qid * 2 + 8];
            }
            uint32_t bf[4][2];
#pragma unroll
            for (int ni = 0; ni < 4; ni++) {
                int cb = wn * 32 + ni * 8 + grp;
                bf[ni][0] = *(const uint32_t*)&B_[cb * BKP + ko + qid * 2];
                bf[ni][1] = *(const uint32_t*)&B_[cb * BKP + ko + qid * 2 + 8];
            }
#pragma unroll
            for (int mi = 0; mi < 4; mi++)
#pragma unroll
                for (int ni = 0; ni < 4; ni++)
                    mma_f16(acc[mi][ni][0], acc[mi][ni][1], acc[mi][ni][2], acc[mi][ni][3],
                            af[mi][0], af[mi][1], af[mi][2], af[mi][3],
                            bf[ni][0], bf[ni][1]);
        }
    }
    __syncthreads();

    // ---- h store (fp16) ----
    __half* hbase = g_h + (size_t)v * NN * HC;
#pragma unroll
    for (int mi = 0; mi < 4; mi++) {
#pragma unroll
        for (int ni = 0; ni < 4; ni++) {
            int nc = nc0 + wn * 32 + ni * 8 + qid * 2;
            int r0 = mbase + wm * 64 + mi * 16 + grp;
            if (r0 < NN)
                *(__half2*)&hbase[(size_t)r0 * HC + nc] =
                    __floats2half2_rn(acc[mi][ni][0], acc[mi][ni][1]);
            int r1 = r0 + 8;
            if (r1 < NN)
                *(__half2*)&hbase[(size_t)r1 * HC + nc] =
                    __floats2half2_rn(acc[mi][ni][2], acc[mi][ni][3]);
        }
    }

    // ---- fused s-scores ----
    float as_[4][2], ad_[4][2];
    const float* asv = a_src + v * HC + nc0;
    const float* adv = a_dst + v * HC + nc0;
#pragma unroll
    for (int ni = 0; ni < 4; ni++) {
        int cb = wn * 32 + ni * 8 + qid * 2;
        as_[ni][0] = asv[cb];     as_[ni][1] = asv[cb + 1];
        ad_[ni][0] = adv[cb];     ad_[ni][1] = adv[cb + 1];
    }
#pragma unroll
    for (int mi = 0; mi < 4; mi++) {
        float ps0 = 0.f, pd0 = 0.f, ps1 = 0.f, pd1 = 0.f;
#pragma unroll
        for (int ni = 0; ni < 4; ni++) {
            ps0 += acc[mi][ni][0] * as_[ni][0] + acc[mi][ni][1] * as_[ni][1];
            pd0 += acc[mi][ni][0] * ad_[ni][0] + acc[mi][ni][1] * ad_[ni][1];
            ps1 += acc[mi][ni][2] * as_[ni][0] + acc[mi][ni][3] * as_[ni][1];
            pd1 += acc[mi][ni][2] * ad_[ni][0] + acc[mi][ni][3] * ad_[ni][1];
        }
#pragma unroll
        for (int off = 1; off <= 2; off <<= 1) {
            ps0 += __shfl_xor_sync(0xFFFFFFFFu, ps0, off);
            pd0 += __shfl_xor_sync(0xFFFFFFFFu, pd0, off);
            ps1 += __shfl_xor_sync(0xFFFFFFFFu, ps1, off);
            pd1 += __shfl_xor_sync(0xFFFFFFFFu, pd1, off);
        }
        if (qid == 0) {
            int rl = wm * 64 + mi * 16 + grp;
            sps[rl][wn] = ps0;      spd[rl][wn] = pd0;
            sps[rl + 8][wn] = ps1;  spd[rl + 8][wn] = pd1;
        }
    }
    __syncthreads();
    if (tid < 128) {
        int row = mbase + tid;
        if (row < NN) {
            float s = sps[tid][0] + sps[tid][1] + sps[tid][2] + sps[tid][3];
            float d = spd[tid][0] + spd[tid][1] + spd[tid][2] + spd[tid][3];
            size_t o = ((size_t)v * NN + row) * HH + head;
            g_ssrc[o] = s;
            g_sdst[o] = d;
        }
    }
}

// ---------------- count histogram (grid.y = view) ----------------
__global__ void count_kernel(const int* __restrict__ e0,
                             const int* __restrict__ e1,
                             const int* __restrict__ e2) {
    int e = blockIdx.x * blockDim.x + threadIdx.x;
    if (e >= TOTE) return;
    int v = blockIdx.y;
    const int* ei = (v == 0) ? e0 : (v == 1) ? e1 : e2;
    int dst = (e < EE) ? ei[EE + e] : (e - EE);
    atomicAdd(&g_count[v * NN + dst], 1);
}

// ---------------- multi-block scan (grid.y = view) ----------------
__global__ void scan1_kernel() {
    __shared__ int sd[1024];
    int b = blockIdx.x, v = blockIdx.y, tid = threadIdx.x;
    int i = b * 1024 + tid;
    int val = (i < NN) ? g_count[v * NN + i] : 0;
    sd[tid] = val;
    __syncthreads();
#pragma unroll
    for (int off = 1; off < 1024; off <<= 1) {
        int t = (tid >= off) ? sd[tid - off] : 0;
        __syncthreads();
        sd[tid] += t;
        __syncthreads();
    }
    if (i < NN) g_indptr[v * (NN + 1) + i] = sd[tid] - val;
    if (tid == 1023) g_btot[v * 64 + b] = sd[1023];
}

__global__ void scan2_kernel(int nb) {
    __shared__ int sd[64];
    int v = blockIdx.x, tid = threadIdx.x;
    int val = (tid < nb) ? g_btot[v * 64 + tid] : 0;
    sd[tid] = val;
    __syncthreads();
#pragma unroll
    for (int off = 1; off < 64; off <<= 1) {
        int t = (tid >= off) ? sd[tid - off] : 0;
        __syncthreads();
        sd[tid] += t;
        __syncthreads();
    }
    g_boff[v * 64 + tid] = sd[tid] - val;
    if (tid == nb - 1) g_indptr[v * (NN + 1) + NN] = sd[tid];
}

__global__ void scan3_kernel() {
    int i = blockIdx.x * blockDim.x + threadIdx.x;
    int v = blockIdx.y;
    if (i < NN) {
        int val = g_indptr[v * (NN + 1) + i] + g_boff[v * 64 + (i >> 10)];
        g_indptr[v * (NN + 1) + i] = val;
        g_cursor[v * NN + i] = val;
    }
}

// ---------------- scatter: exp(leaky) -> CSR (grid.y = view) -------------
__global__ void scatter_kernel(const int* __restrict__ e0,
                               const int* __restrict__ e1,
                               const int* __restrict__ e2) {
    int e = blockIdx.x * blockDim.x + threadIdx.x;
    if (e >= TOTE) return;
    int v = blockIdx.y;
    const int* ei = (v == 0) ? e0 : (v == 1) ? e1 : e2;
    int src, dst;
    if (e < EE) { src = ei[e]; dst = ei[EE + e]; }
    else        { src = dst = e - EE; }
    float4 s4 = *(const float4*)&g_ssrc[((size_t)v * NN + src) * HH];
    float4 d4 = *(const float4*)&g_sdst[((size_t)v * NN + dst) * HH];
    float sc[HH] = { s4.x + d4.x, s4.y + d4.y, s4.z + d4.z, s4.w + d4.w };
    float ex[HH];
#pragma unroll
    for (int hd = 0; hd < HH; hd++) {
        float s = sc[hd];
        s = (s > 0.f) ? s : 0.2f * s;
        ex[hd] = __expf(s);
    }
    int idx = atomicAdd(&g_cursor[v * NN + dst], 1);
    g_csrc[(size_t)v * TOTE + idx] = src;
    *(float4*)&g_cex[((size_t)v * TOTE + idx) * HH] =
        make_float4(ex[0], ex[1], ex[2], ex[3]);
}

// ---------------- aggregate (grid = NN x VV), unroll 2 ----------------
__global__ void aggregate_kernel(const float* __restrict__ bias_all) {
    int dst = blockIdx.x;
    int v = blockIdx.y;
    int tid = threadIdx.x;           // 0..127
    int head = tid >> 5;
    const __half* h = g_h + (size_t)v * NN * HC;
    const int* csrc = g_csrc + (size_t)v * TOTE;
    const float* cex = g_cex + (size_t)v * TOTE * HH;

    float a0 = 0.f, a1 = 0.f, a2 = 0.f, a3 = 0.f, dsum = 0.f;
    int beg = g_indptr[v * (NN + 1) + dst];
    int end = g_indptr[v * (NN + 1) + dst + 1];
    int i = beg;
    for (; i + 2 <= end; i += 2) {
        int s0 = csrc[i];
        int s1 = csrc[i + 1];
        float e0 = cex[(size_t)i * HH + head];
        float e1 = cex[(size_t)(i + 1) * HH + head];
        uint2 u0 = *(const uint2*)&h[(size_t)s0 * HC + tid * 4];
        uint2 u1 = *(const uint2*)&h[(size_t)s1 * HC + tid * 4];
        float2 p0 = __half22float2(*(__half2*)&u0.x);
        float2 p1 = __half22float2(*(__half2*)&u0.y);
        float2 q0 = __half22float2(*(__half2*)&u1.x);
        float2 q1 = __half22float2(*(__half2*)&u1.y);
        a0 += e0 * p0.x + e1 * q0.x;
        a1 += e0 * p0.y + e1 * q0.y;
        a2 += e0 * p1.x + e1 * q1.x;
        a3 += e0 * p1.y + e1 * q1.y;
        dsum += e0 + e1;
    }
    if (i < end) {
        int s0 = csrc[i];
        float e0 = cex[(size_t)i * HH + head];
        uint2 u0 = *(const uint2*)&h[(size_t)s0 * HC + tid * 4];
        float2 p0 = __half22float2(*(__half2*)&u0.x);
        float2 p1 = __half22float2(*(__half2*)&u0.y);
        a0 += e0 * p0.x;
        a1 += e0 * p0.y;
        a2 += e0 * p1.x;
        a3 += e0 * p1.y;
        dsum += e0;
    }
    float inv = 1.0f / fmaxf(dsum, 1e-16f);
    __shared__ float s[HC];
    s[tid * 4 + 0] = a0 * inv;
    s[tid * 4 + 1] = a1 * inv;
    s[tid * 4 + 2] = a2 * inv;
    s[tid * 4 + 3] = a3 * inv;
    __syncthreads();
    float val = 0.25f * (s[tid] + s[tid + 128] + s[tid + 256] + s[tid + 384])
              + bias_all[v * CC + tid];
    val = (val > 0.f) ? val : expm1f(val);
    g_views[(size_t)v * NN * CC + (size_t)dst * CC + tid] = val;
}

// ---------------- fusion + classifier: one warp per node -----------------
__global__ void fusion_kernel(const float* __restrict__ fw,
                              const float* __restrict__ fb,
                              const float* __restrict__ w1,
                              const float* __restrict__ b1,
                              const float* __restrict__ w2,
                              const float* __restrict__ b2,
                              float* __restrict__ out_logits,
                              float* __restrict__ out_w) {
    __shared__ float w1s[CC * 64];
    __shared__ float fws[CC];
    __shared__ float w2s[CC];
    __shared__ float sfused[8][CC];
    __shared__ float sh1[8][64];

    int tid = threadIdx.x;             // 256 = 8 warps
    int warp = tid >> 5, lane = tid & 31;
    for (int i = tid; i < CC * 64; i += 256) w1s[i] = w1[i];
    if (tid < CC) fws[tid] = fw[tid];
    if (tid < CC) w2s[tid] = w2[tid];
    __syncthreads();

    int node = blockIdx.x * 8 + warp;
    if (node >= NN) return;

    const size_t NSTR = (size_t)NN * CC;
    const float* vbase = g_views + (size_t)node * CC;

    float v0[4], v1[4], v2[4];
    float p0 = 0.f, p1 = 0.f, p2 = 0.f;
#pragma unroll
    for (int k = 0; k < 4; k++) {
        int c = lane + 32 * k;
        v0[k] = vbase[c];
        v1[k] = vbase[NSTR + c];
        v2[k] = vbase[2 * NSTR + c];
        float f = fws[c];
        p0 += v0[k] * f;
        p1 += v1[k] * f;
        p2 += v2[k] * f;
    }
#pragma unroll
    for (int off = 16; off; off >>= 1) {
        p0 += __shfl_xor_sync(0xFFFFFFFFu, p0, off);
        p1 += __shfl_xor_sync(0xFFFFFFFFu, p1, off);
        p2 += __shfl_xor_sync(0xFFFFFFFFu, p2, off);
    }
    float fbv = fb[0];
    float s0 = p0 + fbv, s1 = p1 + fbv, s2 = p2 + fbv;
    float mx = fmaxf(s0, fmaxf(s1, s2));
    float e0 = expf(s0 - mx), e1 = expf(s1 - mx), e2 = expf(s2 - mx);
    float inv = 1.0f / (e0 + e1 + e2);
    float w0 = e0 * inv, w1v = e1 * inv, w2v = e2 * inv;
    if (lane == 0) {
        out_w[node * 3 + 0] = w0;
        out_w[node * 3 + 1] = w1v;
        out_w[node * 3 + 2] = w2v;
    }
#pragma unroll
    for (int k = 0; k < 4; k++)
        sfused[warp][lane + 32 * k] = w0 * v0[k] + w1v * v1[k] + w2v * v2[k];
    __syncwarp();

    float acc0 = b1[lane], acc1 = b1[lane + 32];
#pragma unroll 8
    for (int c = 0; c < CC; c++) {
        float fv = sfused[warp][c];
        acc0 += fv * w1s[c * 64 + lane];
        acc1 += fv * w1s[c * 64 + lane + 32];
    }
    sh1[warp][lane] = fmaxf(acc0, 0.f);
    sh1[warp][lane + 32] = fmaxf(acc1, 0.f);
    __syncwarp();

    float ha = sh1[warp][lane], hb = sh1[warp][lane + 32];
    float q0 = ha * w2s[lane * 2] + hb * w2s[(lane + 32) * 2];
    float q1 = ha * w2s[lane * 2 + 1] + hb * w2s[(lane + 32) * 2 + 1];
#pragma unroll
    for (int off = 16; off; off >>= 1) {
        q0 += __shfl_xor_sync(0xFFFFFFFFu, q0, off);
        q1 += __shfl_xor_sync(0xFFFFFFFFu, q1, off);
    }
    if (lane == 0)
        *(float2*)&out_logits[node * 2] = make_float2(q0 + b2[0], q1 + b2[1]);
}

// ---------------- launcher (single stream) ----------------
extern "C" void kernel_launch(void* const* d_in, const int* in_sizes, int n_in,
                              void* d_out, int out_size) {
    const float* x     = (const float*)d_in[0];
    const int*   ei0   = (const int*)d_in[1];
    const int*   ei1   = (const int*)d_in[2];
    const int*   ei2   = (const int*)d_in[3];
    const float* W     = (const float*)d_in[4];
    const float* a_src = (const float*)d_in[5];
    const float* a_dst = (const float*)d_in[6];
    const float* b     = (const float*)d_in[7];
    const float* fus_w = (const float*)d_in[8];
    const float* fus_b = (const float*)d_in[9];
    const float* w1    = (const float*)d_in[10];
    const float* b1    = (const float*)d_in[11];
    const float* w2    = (const float*)d_in[12];
    const float* b2    = (const float*)d_in[13];
    float* out = (float*)d_out;

    static int smem_set = 0;
    if (!smem_set) {
        cudaFuncSetAttribute(gemm_f16_kernel,
                             cudaFuncAttributeMaxDynamicSharedMemorySize,
                             GEMM_DYN_SMEM);
        smem_set = 1;
    }

    void* count_ptr;
    cudaGetSymbolAddress(&count_ptr, g_count);

    int nb = (NN + 1023) / 1024;
    dim3 egrid((TOTE + 255) / 256, VV);
    dim3 gemm_grid(GN / 128, (NN + 127) / 128);

    xcvt_kernel<<<(NN * FIN / 4 + 255) / 256, 256>>>(x);
    wcvt_kernel<<<(VV * HC * FIN + 255) / 256, 256>>>(W);
    cudaMemsetAsync(count_ptr, 0, (size_t)VV * NN * sizeof(int));
    count_kernel<<<egrid, 256>>>(ei0, ei1, ei2);
    gemm_f16_kernel<<<gemm_grid, 256, GEMM_DYN_SMEM>>>(a_src, a_dst);
    scan1_kernel<<<dim3(nb, VV), 1024>>>();
    scan2_kernel<<<VV, 64>>>(nb);
    scan3_kernel<<<dim3((NN + 255) / 256, VV), 256>>>();
    scatter_kernel<<<egrid, 256>>>(ei0, ei1, ei2);
    aggregate_kernel<<<dim3(NN, VV), 128>>>(b);

    fusion_kernel<<<(NN + 7) / 8, 256>>>(fus_w, fus_b, w1, b1, w2, b2,
                                         out, out + NN * 2);
}

// round 16
// speedup vs baseline: 1.1617x; 1.1617x over previous
#include <cuda_runtime.h>
#include <cuda_fp16.h>
#include <math.h>
#include <stdint.h>

// ---------------- problem constants ----------------
#define NN      50000
#define EE      800000
#define TOTE    (EE + NN)      // 850000 edges incl self loops
#define FIN     256
#define HH      4
#define CC      128
#define HC      (HH * CC)      // 512
#define VV      3
#define GN      (VV * HC)      // 1536
#define NK      8              // K chunks of 32

// ---------------- device scratch ----------------
__device__ __half g_h[(size_t)VV * NN * HC];      // 153.6 MB
__device__ __half g_xf16[(size_t)NN * FIN];       // 25.6 MB
__device__ __half g_wf16[(size_t)VV * HC * FIN];  // 0.79 MB (Wt[v][n][k])
__device__ float g_views[(size_t)VV * NN * CC];   // 76.8 MB
__device__ float g_ssrc[(size_t)VV * NN * HH];
__device__ float g_sdst[(size_t)VV * NN * HH];
__device__ int   g_count[VV * NN];
__device__ int   g_cursor[VV * NN];
__device__ int   g_indptr[VV * (NN + 1)];
__device__ int   g_btot[VV * 64];
__device__ int   g_boff[VV * 64];
__device__ int   g_csrc[VV * TOTE];
__device__ float g_cex[(size_t)VV * TOTE * HH];   // 40.8 MB

// ---------------- helpers ----------------
__device__ __forceinline__ uint32_t smem_u32(const void* p) {
    uint32_t a;
    asm("{ .reg .u64 t; cvta.to.shared.u64 t, %1; cvt.u32.u64 %0, t; }"
        : "=r"(a) : "l"(p));
    return a;
}

// 16B async copy, L1-bypass (.cg). pred=false -> zero-fill.
__device__ __forceinline__ void cp16(uint32_t dst, const void* src, bool pred) {
    int bytes = pred ? 16 : 0;
    asm volatile("cp.async.cg.shared.global [%0], [%1], 16, %2;"
                 :: "r"(dst), "l"(src), "r"(bytes));
}

__device__ __forceinline__ void mma_f16(float& c0, float& c1, float& c2, float& c3,
                                        uint32_t a0, uint32_t a1, uint32_t a2, uint32_t a3,
                                        uint32_t b0, uint32_t b1) {
    asm volatile(
        "mma.sync.aligned.m16n8k16.row.col.f32.f16.f16.f32 "
        "{%0,%1,%2,%3}, {%4,%5,%6,%7}, {%8,%9}, {%0,%1,%2,%3};"
        : "+f"(c0), "+f"(c1), "+f"(c2), "+f"(c3)
        : "r"(a0), "r"(a1), "r"(a2), "r"(a3), "r"(b0), "r"(b1));
}

// ---------------- 0) precision converts ----------------
__global__ void xcvt_kernel(const float* __restrict__ x) {
    int i = blockIdx.x * blockDim.x + threadIdx.x;
    if (i < NN * FIN / 4) {
        float4 v = *(const float4*)&x[(size_t)i * 4];
        uint2 o;
        ((__half2*)&o)[0] = __floats2half2_rn(v.x, v.y);
        ((__half2*)&o)[1] = __floats2half2_rn(v.z, v.w);
        *(uint2*)&g_xf16[(size_t)i * 4] = o;
    }
}

__global__ void wcvt_kernel(const float* __restrict__ W) {
    int i = blockIdx.x * blockDim.x + threadIdx.x;   // Wt[v][n][k]
    if (i < VV * HC * FIN) {
        int k = i & (FIN - 1);
        int n = (i >> 8) & (HC - 1);
        int v = i >> 17;
        g_wf16[i] = __float2half(W[((size_t)v * FIN + k) * HC + n]);
    }
}

// ---------------- 1) fp16 HMMA GEMM, 3-stage cp.async, 1 sync/iter -------
// BM=128 BN=128 BK=32; 256 thr = 8 warps (2m x 4n); warp tile 64x32.
#define AKP 40
#define BKP 40
#define ASTAGE (128 * AKP)     // halves per stage
#define BSTAGE (128 * BKP)
#define ABYTES (ASTAGE * 2)
#define BBYTES (BSTAGE * 2)
#define GEMM_DYN_SMEM (3 * (ABYTES + BBYTES))   // 61440 B
__global__ void gemm_f16_kernel(const float* __restrict__ a_src,
                                const float* __restrict__ a_dst) {
    extern __shared__ __half dyn_smem[];
    __half* As = dyn_smem;                    // 3 stages
    __half* Bt = dyn_smem + 3 * ASTAGE;       // 3 stages
    __shared__ float sps[128][4];
    __shared__ float spd[128][4];

    int tid = threadIdx.x;
    int warp = tid >> 5, lane = tid & 31;
    int wm = warp >> 2, wn = warp & 3;
    int grp = lane >> 2, qid = lane & 3;

    int mbase = blockIdx.y * 128;
    int nbase = blockIdx.x * 128;
    int v = nbase >> 9;
    int nc0 = nbase & 511;
    int head = nc0 >> 7;
    const __half* Ax = g_xf16;
    const __half* Bw = g_wf16 + (size_t)v * HC * FIN + (size_t)nc0 * FIN;

    uint32_t as_b = smem_u32(As);
    uint32_t bt_b = smem_u32(Bt);

    int r0l = tid >> 2;
    int r1l = r0l + 64;
    int ul  = (tid & 3) * 8;
    int row0 = mbase + r0l, row1 = mbase + r1l;
    bool p0 = row0 < NN, p1 = row1 < NN;
    const __half* a0p = &Ax[(size_t)(p0 ? row0 : 0) * FIN + ul];
    const __half* a1p = &Ax[(size_t)(p1 ? row1 : 0) * FIN + ul];
    const __half* b0p = &Bw[(size_t)r0l * FIN + ul];
    const __half* b1p = &Bw[(size_t)r1l * FIN + ul];
    uint32_t asd0 = as_b + (uint32_t)((r0l * AKP + ul) * 2);
    uint32_t asd1 = as_b + (uint32_t)((r1l * AKP + ul) * 2);
    uint32_t btd0 = bt_b + (uint32_t)((r0l * BKP + ul) * 2);
    uint32_t btd1 = bt_b + (uint32_t)((r1l * BKP + ul) * 2);

    float acc[4][4][4];
#pragma unroll
    for (int mi = 0; mi < 4; mi++)
#pragma unroll
        for (int ni = 0; ni < 4; ni++)
#pragma unroll
            for (int r = 0; r < 4; r++) acc[mi][ni][r] = 0.0f;

    cp16(asd0, a0p, p0);
    cp16(asd1, a1p, p1);
    cp16(btd0, b0p, true);
    cp16(btd1, b1p, true);
    asm volatile("cp.async.commit_group;" ::: "memory");
    cp16(asd0 + ABYTES, a0p + 32, p0);
    cp16(asd1 + ABYTES, a1p + 32, p1);
    cp16(btd0 + BBYTES, b0p + 32, true);
    cp16(btd1 + BBYTES, b1p + 32, true);
    asm volatile("cp.async.commit_group;" ::: "memory");

    for (int c = 0; c < NK; c++) {
        if (c == NK - 1)
            asm volatile("cp.async.wait_group 0;" ::: "memory");
        else
            asm volatile("cp.async.wait_group 1;" ::: "memory");
        __syncthreads();

        if (c + 2 < NK) {
            int k0 = (c + 2) * 32;
            uint32_t st = (uint32_t)((c + 2) % 3);
            uint32_t soA = st * ABYTES;
            uint32_t soB = st * BBYTES;
            cp16(asd0 + soA, a0p + k0, p0);
            cp16(asd1 + soA, a1p + k0, p1);
            cp16(btd0 + soB, b0p + k0, true);
            cp16(btd1 + soB, b1p + k0, true);
            asm volatile("cp.async.commit_group;" ::: "memory");
        }

        const __half* A_ = &As[(c % 3) * ASTAGE];
        const __half* B_ = &Bt[(c % 3) * BSTAGE];
#pragma unroll
        for (int kk = 0; kk < 2; kk++) {
            int ko = kk * 16;
            uint32_t af[4][4];
#pragma unroll
            for (int mi = 0; mi < 4; mi++) {
                int r0 = wm * 64 + mi * 16 + grp;
                af[mi][0] = *(const uint32_t*)&A_[r0 * AKP + ko + qid * 2];
                af[mi][1] = *(const uint32_t*)&A_[(r0 + 8) * AKP + ko + qid * 2];
                af[mi][2] = *(const uint32_t*)&A_[r0 * AKP + ko + qid * 2 + 8];
                af[mi][3] = *(const uint32_t*)&A_[(r0 + 8) * AKP + ko + qid * 2 + 8];
            }
            uint32_t bf[4][2];
#pragma unroll
            for (int ni = 0; ni < 4; ni++) {
                int cb = wn * 32 + ni * 8 + grp;
                bf[ni][0] = *(const uint32_t*)&B_[cb * BKP + ko + qid * 2];
                bf[ni][1] = *(const uint32_t*)&B_[cb * BKP + ko + qid * 2 + 8];
            }
#pragma unroll
            for (int mi = 0; mi < 4; mi++)
#pragma unroll
                for (int ni = 0; ni < 4; ni++)
                    mma_f16(acc[mi][ni][0], acc[mi][ni][1], acc[mi][ni][2], acc[mi][ni][3],
                            af[mi][0], af[mi][1], af[mi][2], af[mi][3],
                            bf[ni][0], bf[ni][1]);
        }
    }
    __syncthreads();

    // ---- h store (fp16) ----
    __half* hbase = g_h + (size_t)v * NN * HC;
#pragma unroll
    for (int mi = 0; mi < 4; mi++) {
#pragma unroll
        for (int ni = 0; ni < 4; ni++) {
            int nc = nc0 + wn * 32 + ni * 8 + qid * 2;
            int r0 = mbase + wm * 64 + mi * 16 + grp;
            if (r0 < NN)
                *(__half2*)&hbase[(size_t)r0 * HC + nc] =
                    __floats2half2_rn(acc[mi][ni][0], acc[mi][ni][1]);
            int r1 = r0 + 8;
            if (r1 < NN)
                *(__half2*)&hbase[(size_t)r1 * HC + nc] =
                    __floats2half2_rn(acc[mi][ni][2], acc[mi][ni][3]);
        }
    }

    // ---- fused s-scores ----
    float as_[4][2], ad_[4][2];
    const float* asv = a_src + v * HC + nc0;
    const float* adv = a_dst + v * HC + nc0;
#pragma unroll
    for (int ni = 0; ni < 4; ni++) {
        int cb = wn * 32 + ni * 8 + qid * 2;
        as_[ni][0] = asv[cb];     as_[ni][1] = asv[cb + 1];
        ad_[ni][0] = adv[cb];     ad_[ni][1] = adv[cb + 1];
    }
#pragma unroll
    for (int mi = 0; mi < 4; mi++) {
        float ps0 = 0.f, pd0 = 0.f, ps1 = 0.f, pd1 = 0.f;
#pragma unroll
        for (int ni = 0; ni < 4; ni++) {
            ps0 += acc[mi][ni][0] * as_[ni][0] + acc[mi][ni][1] * as_[ni][1];
            pd0 += acc[mi][ni][0] * ad_[ni][0] + acc[mi][ni][1] * ad_[ni][1];
            ps1 += acc[mi][ni][2] * as_[ni][0] + acc[mi][ni][3] * as_[ni][1];
            pd1 += acc[mi][ni][2] * ad_[ni][0] + acc[mi][ni][3] * ad_[ni][1];
        }
#pragma unroll
        for (int off = 1; off <= 2; off <<= 1) {
            ps0 += __shfl_xor_sync(0xFFFFFFFFu, ps0, off);
            pd0 += __shfl_xor_sync(0xFFFFFFFFu, pd0, off);
            ps1 += __shfl_xor_sync(0xFFFFFFFFu, ps1, off);
            pd1 += __shfl_xor_sync(0xFFFFFFFFu, pd1, off);
        }
        if (qid == 0) {
            int rl = wm * 64 + mi * 16 + grp;
            sps[rl][wn] = ps0;      spd[rl][wn] = pd0;
            sps[rl + 8][wn] = ps1;  spd[rl + 8][wn] = pd1;
        }
    }
    __syncthreads();
    if (tid < 128) {
        int row = mbase + tid;
        if (row < NN) {
            float s = sps[tid][0] + sps[tid][1] + sps[tid][2] + sps[tid][3];
            float d = spd[tid][0] + spd[tid][1] + spd[tid][2] + spd[tid][3];
            size_t o = ((size_t)v * NN + row) * HH + head;
            g_ssrc[o] = s;
            g_sdst[o] = d;
        }
    }
}

// ---------------- count histogram (grid.y = view) ----------------
__global__ void count_kernel(const int* __restrict__ e0,
                             const int* __restrict__ e1,
                             const int* __restrict__ e2) {
    int e = blockIdx.x * blockDim.x + threadIdx.x;
    if (e >= TOTE) return;
    int v = blockIdx.y;
    const int* ei = (v == 0) ? e0 : (v == 1) ? e1 : e2;
    int dst = (e < EE) ? ei[EE + e] : (e - EE);
    atomicAdd(&g_count[v * NN + dst], 1);
}

// ---------------- multi-block scan (grid.y = view) ----------------
__global__ void scan1_kernel() {
    __shared__ int sd[1024];
    int b = blockIdx.x, v = blockIdx.y, tid = threadIdx.x;
    int i = b * 1024 + tid;
    int val = (i < NN) ? g_count[v * NN + i] : 0;
    sd[tid] = val;
    __syncthreads();
#pragma unroll
    for (int off = 1; off < 1024; off <<= 1) {
        int t = (tid >= off) ? sd[tid - off] : 0;
        __syncthreads();
        sd[tid] += t;
        __syncthreads();
    }
    if (i < NN) g_indptr[v * (NN + 1) + i] = sd[tid] - val;
    if (tid == 1023) g_btot[v * 64 + b] = sd[1023];
}

__global__ void scan2_kernel(int nb) {
    __shared__ int sd[64];
    int v = blockIdx.x, tid = threadIdx.x;
    int val = (tid < nb) ? g_btot[v * 64 + tid] : 0;
    sd[tid] = val;
    __syncthreads();
#pragma unroll
    for (int off = 1; off < 64; off <<= 1) {
        int t = (tid >= off) ? sd[tid - off] : 0;
        __syncthreads();
        sd[tid] += t;
        __syncthreads();
    }
    g_boff[v * 64 + tid] = sd[tid] - val;
    if (tid == nb - 1) g_indptr[v * (NN + 1) + NN] = sd[tid];
}

__global__ void scan3_kernel() {
    int i = blockIdx.x * blockDim.x + threadIdx.x;
    int v = blockIdx.y;
    if (i < NN) {
        int val = g_indptr[v * (NN + 1) + i] + g_boff[v * 64 + (i >> 10)];
        g_indptr[v * (NN + 1) + i] = val;
        g_cursor[v * NN + i] = val;
    }
}

// ---------------- scatter: exp(leaky) -> CSR (grid.y = view) -------------
__global__ void scatter_kernel(const int* __restrict__ e0,
                               const int* __restrict__ e1,
                               const int* __restrict__ e2) {
    int e = blockIdx.x * blockDim.x + threadIdx.x;
    if (e >= TOTE) return;
    int v = blockIdx.y;
    const int* ei = (v == 0) ? e0 : (v == 1) ? e1 : e2;
    int src, dst;
    if (e < EE) { src = ei[e]; dst = ei[EE + e]; }
    else        { src = dst = e - EE; }
    float4 s4 = *(const float4*)&g_ssrc[((size_t)v * NN + src) * HH];
    float4 d4 = *(const float4*)&g_sdst[((size_t)v * NN + dst) * HH];
    float sc[HH] = { s4.x + d4.x, s4.y + d4.y, s4.z + d4.z, s4.w + d4.w };
    float ex[HH];
#pragma unroll
    for (int hd = 0; hd < HH; hd++) {
        float s = sc[hd];
        s = (s > 0.f) ? s : 0.2f * s;
        ex[hd] = __expf(s);
    }
    int idx = atomicAdd(&g_cursor[v * NN + dst], 1);
    g_csrc[(size_t)v * TOTE + idx] = src;
    *(float4*)&g_cex[((size_t)v * TOTE + idx) * HH] =
        make_float4(ex[0], ex[1], ex[2], ex[3]);
}

// ---------------- aggregate: 64 thr/block, uint4 loads, unroll 2 ---------
__global__ void aggregate_kernel(const float* __restrict__ bias_all) {
    int dst = blockIdx.x;
    int v = blockIdx.y;
    int tid = threadIdx.x;           // 0..63, owns channels 8t..8t+7
    int head = tid >> 4;             // 8 channels lie within one head
    const __half* h = g_h + (size_t)v * NN * HC;
    const int* csrc = g_csrc + (size_t)v * TOTE;
    const float* cex = g_cex + (size_t)v * TOTE * HH;

    float a[8];
#pragma unroll
    for (int j = 0; j < 8; j++) a[j] = 0.f;
    float dsum = 0.f;

    int beg = g_indptr[v * (NN + 1) + dst];
    int end = g_indptr[v * (NN + 1) + dst + 1];
    int i = beg;
    for (; i + 2 <= end; i += 2) {
        int s0 = csrc[i];
        int s1 = csrc[i + 1];
        float e0 = cex[(size_t)i * HH + head];
        float e1 = cex[(size_t)(i + 1) * HH + head];
        uint4 u0 = *(const uint4*)&h[(size_t)s0 * HC + tid * 8];
        uint4 u1 = *(const uint4*)&h[(size_t)s1 * HC + tid * 8];
        const uint32_t* w0 = (const uint32_t*)&u0;
        const uint32_t* w1 = (const uint32_t*)&u1;
#pragma unroll
        for (int j = 0; j < 4; j++) {
            float2 f0 = __half22float2(*(const __half2*)&w0[j]);
            float2 f1 = __half22float2(*(const __half2*)&w1[j]);
            a[2 * j]     += e0 * f0.x + e1 * f1.x;
            a[2 * j + 1] += e0 * f0.y + e1 * f1.y;
        }
        dsum += e0 + e1;
    }
    if (i < end) {
        int s0 = csrc[i];
        float e0 = cex[(size_t)i * HH + head];
        uint4 u0 = *(const uint4*)&h[(size_t)s0 * HC + tid * 8];
        const uint32_t* w0 = (const uint32_t*)&u0;
#pragma unroll
        for (int j = 0; j < 4; j++) {
            float2 f0 = __half22float2(*(const __half2*)&w0[j]);
            a[2 * j]     += e0 * f0.x;
            a[2 * j + 1] += e0 * f0.y;
        }
        dsum += e0;
    }
    float inv = 1.0f / fmaxf(dsum, 1e-16f);
    __shared__ float s[HC];
#pragma unroll
    for (int j = 0; j < 8; j++) s[tid * 8 + j] = a[j] * inv;
    __syncthreads();
#pragma unroll
    for (int c0 = 0; c0 < CC; c0 += 64) {
        int c = c0 + tid;
        float val = 0.25f * (s[c] + s[c + 128] + s[c + 256] + s[c + 384])
                  + bias_all[v * CC + c];
        val = (val > 0.f) ? val : expm1f(val);
        g_views[(size_t)v * NN * CC + (size_t)dst * CC + c] = val;
    }
}

// ---------------- fusion + classifier: one warp per node -----------------
__global__ void fusion_kernel(const float* __restrict__ fw,
                              const float* __restrict__ fb,
                              const float* __restrict__ w1,
                              const float* __restrict__ b1,
                              const float* __restrict__ w2,
                              const float* __restrict__ b2,
                              float* __restrict__ out_logits,
                              float* __restrict__ out_w) {
    __shared__ float w1s[CC * 64];
    __shared__ float fws[CC];
    __shared__ float w2s[CC];
    __shared__ float sfused[8][CC];
    __shared__ float sh1[8][64];

    int tid = threadIdx.x;             // 256 = 8 warps
    int warp = tid >> 5, lane = tid & 31;
    for (int i = tid; i < CC * 64; i += 256) w1s[i] = w1[i];
    if (tid < CC) fws[tid] = fw[tid];
    if (tid < CC) w2s[tid] = w2[tid];
    __syncthreads();

    int node = blockIdx.x * 8 + warp;
    if (node >= NN) return;

    const size_t NSTR = (size_t)NN * CC;
    const float* vbase = g_views + (size_t)node * CC;

    float v0[4], v1[4], v2[4];
    float p0 = 0.f, p1 = 0.f, p2 = 0.f;
#pragma unroll
    for (int k = 0; k < 4; k++) {
        int c = lane + 32 * k;
        v0[k] = vbase[c];
        v1[k] = vbase[NSTR + c];
        v2[k] = vbase[2 * NSTR + c];
        float f = fws[c];
        p0 += v0[k] * f;
        p1 += v1[k] * f;
        p2 += v2[k] * f;
    }
#pragma unroll
    for (int off = 16; off; off >>= 1) {
        p0 += __shfl_xor_sync(0xFFFFFFFFu, p0, off);
        p1 += __shfl_xor_sync(0xFFFFFFFFu, p1, off);
        p2 += __shfl_xor_sync(0xFFFFFFFFu, p2, off);
    }
    float fbv = fb[0];
    float s0 = p0 + fbv, s1 = p1 + fbv, s2 = p2 + fbv;
    float mx = fmaxf(s0, fmaxf(s1, s2));
    float e0 = expf(s0 - mx), e1 = expf(s1 - mx), e2 = expf(s2 - mx);
    float inv = 1.0f / (e0 + e1 + e2);
    float w0 = e0 * inv, w1v = e1 * inv, w2v = e2 * inv;
    if (lane == 0) {
        out_w[node * 3 + 0] = w0;
        out_w[node * 3 + 1] = w1v;
        out_w[node * 3 + 2] = w2v;
    }
#pragma unroll
    for (int k = 0; k < 4; k++)
        sfused[warp][lane + 32 * k] = w0 * v0[k] + w1v * v1[k] + w2v * v2[k];
    __syncwarp();

    float acc0 = b1[lane], acc1 = b1[lane + 32];
#pragma unroll 8
    for (int c = 0; c < CC; c++) {
        float fv = sfused[warp][c];
        acc0 += fv * w1s[c * 64 + lane];
        acc1 += fv * w1s[c * 64 + lane + 32];
    }
    sh1[warp][lane] = fmaxf(acc0, 0.f);
    sh1[warp][lane + 32] = fmaxf(acc1, 0.f);
    __syncwarp();

    float ha = sh1[warp][lane], hb = sh1[warp][lane + 32];
    float q0 = ha * w2s[lane * 2] + hb * w2s[(lane + 32) * 2];
    float q1 = ha * w2s[lane * 2 + 1] + hb * w2s[(lane + 32) * 2 + 1];
#pragma unroll
    for (int off = 16; off; off >>= 1) {
        q0 += __shfl_xor_sync(0xFFFFFFFFu, q0, off);
        q1 += __shfl_xor_sync(0xFFFFFFFFu, q1, off);
    }
    if (lane == 0)
        *(float2*)&out_logits[node * 2] = make_float2(q0 + b2[0], q1 + b2[1]);
}

// ---------------- launcher (single stream) ----------------
extern "C" void kernel_launch(void* const* d_in, const int* in_sizes, int n_in,
                              void* d_out, int out_size) {
    const float* x     = (const float*)d_in[0];
    const int*   ei0   = (const int*)d_in[1];
    const int*   ei1   = (const int*)d_in[2];
    const int*   ei2   = (const int*)d_in[3];
    const float* W     = (const float*)d_in[4];
    const float* a_src = (const float*)d_in[5];
    const float* a_dst = (const float*)d_in[6];
    const float* b     = (const float*)d_in[7];
    const float* fus_w = (const float*)d_in[8];
    const float* fus_b = (const float*)d_in[9];
    const float* w1    = (const float*)d_in[10];
    const float* b1    = (const float*)d_in[11];
    const float* w2    = (const float*)d_in[12];
    const float* b2    = (const float*)d_in[13];
    float* out = (float*)d_out;

    static int smem_set = 0;
    if (!smem_set) {
        cudaFuncSetAttribute(gemm_f16_kernel,
                             cudaFuncAttributeMaxDynamicSharedMemorySize,
                             GEMM_DYN_SMEM);
        smem_set = 1;
    }

    void* count_ptr;
    cudaGetSymbolAddress(&count_ptr, g_count);

    int nb = (NN + 1023) / 1024;
    dim3 egrid((TOTE + 255) / 256, VV);
    dim3 gemm_grid(GN / 128, (NN + 127) / 128);

    xcvt_kernel<<<(NN * FIN / 4 + 255) / 256, 256>>>(x);
    wcvt_kernel<<<(VV * HC * FIN + 255) / 256, 256>>>(W);
    cudaMemsetAsync(count_ptr, 0, (size_t)VV * NN * sizeof(int));
    count_kernel<<<egrid, 256>>>(ei0, ei1, ei2);
    gemm_f16_kernel<<<gemm_grid, 256, GEMM_DYN_SMEM>>>(a_src, a_dst);
    scan1_kernel<<<dim3(nb, VV), 1024>>>();
    scan2_kernel<<<VV, 64>>>(nb);
    scan3_kernel<<<dim3((NN + 255) / 256, VV), 256>>>();
    scatter_kernel<<<egrid, 256>>>(ei0, ei1, ei2);
    aggregate_kernel<<<dim3(NN, VV), 64>>>(b);

    fusion_kernel<<<(NN + 7) / 8, 256>>>(fus_w, fus_b, w1, b1, w2, b2,
                                         out, out + NN * 2);
}